// round 15
// baseline (speedup 1.0000x reference)
#include <cuda_runtime.h>

// Problem constants (fixed by setup_inputs)
#define BHALF  4096
#define NTOT   8192
#define DIMS   256
#define NSLOT  64
#define NGROUP 4
#define GBLK   512          // 8-row norm chunks over first half

// fp8 quantization: zn * 8 -> e4m3.  S_fp8 = 64*S.  exp(2S) = exp2(S_fp8*(2/ln2)/64)
#define QSCALE   8.0f
#define EXP2K    0.04508422002778011f

// Block-role layout
#define NORMBLK  1024                     // 8 rows each
#define DENBLK   2080
#define LOGBASE  (NORMBLK + DENBLK)       // 3104: 64 logden roles
#define VPBASE   (LOGBASE + 64)           // 3168: 128 vpart roles
#define CNTBASE  (VPBASE + 128)           // 3296: 4 count roles
#define NBLK_ALL (CNTBASE + 4)            // 3300
#define NRED     196                      // reduce-role count (64+128+4)

// ---------------------------------------------------------------------------
// Scratch (device globals; no allocations allowed)
// ---------------------------------------------------------------------------
__device__ __align__(1024) unsigned char g_zq[(size_t)NTOT * DIMS];  // e4m3*8, swizzled tiles (2 MB)
__device__ float g_den[(size_t)NSLOT * NTOT];                        // slot-major, 2 MB
__device__ float g_pospart[32];
__device__ float g_vpart[NGROUP * GBLK * DIMS];
__device__ float g_vpart2[NGROUP * 32 * DIMS];
__device__ float g_logpart[64];
__device__ int   g_counts[NGROUP];
__device__ int   g_tile_ready[64];   // norm -> den (16 arrivals per tile)
__device__ int   g_dentile[64];      // den  -> logden (64 arrivals per tile)
__device__ int   g_normdone = 0;     // norm -> vpart roles (1024 arrivals)
__device__ int   g_denarrive = 0;
__device__ int   g_arrive = 0;       // reduce-role arrivals (final assembly)

// ---------------------------------------------------------------------------
// PTX helpers (family-portable: cp.async, ldmatrix, mma.sync fp8, ex2.approx)
// ---------------------------------------------------------------------------
__device__ __forceinline__ unsigned smem_u32(const void* p) {
    unsigned a;
    asm("{ .reg .u64 t; cvta.to.shared.u64 t, %1; cvt.u32.u64 %0, t; }" : "=r"(a) : "l"(p));
    return a;
}
__device__ __forceinline__ void cp16(unsigned dst, const void* src) {
    asm volatile("cp.async.cg.shared.global [%0], [%1], 16;" :: "r"(dst), "l"(src) : "memory");
}
#define CP_COMMIT() asm volatile("cp.async.commit_group;" ::: "memory")
#define CP_WAIT(n)  asm volatile("cp.async.wait_group %0;" :: "n"(n) : "memory")

#define LDSM4(r0, r1, r2, r3, a)                                              \
    asm volatile("ldmatrix.sync.aligned.m8n8.x4.shared.b16 {%0,%1,%2,%3}, [%4];" \
                 : "=r"(r0), "=r"(r1), "=r"(r2), "=r"(r3) : "r"(a))

#define MMAFP8(d, a, b0, b1)                                                  \
    asm volatile("mma.sync.aligned.m16n8k32.row.col.f32.e4m3.e4m3.f32 "       \
                 "{%0,%1,%2,%3}, {%4,%5,%6,%7}, {%8,%9}, {%0,%1,%2,%3};"      \
                 : "+f"((d)[0]), "+f"((d)[1]), "+f"((d)[2]), "+f"((d)[3])     \
                 : "r"((a)[0]), "r"((a)[1]), "r"((a)[2]), "r"((a)[3]),        \
                   "r"(b0), "r"(b1))

__device__ __forceinline__ float fexp2q(float s) {
    float r;
    asm("ex2.approx.f32 %0, %1;" : "=f"(r) : "f"(s * EXP2K));
    return r;
}

__device__ __forceinline__ int ld_acquire(const int* p) {
    int v;
    asm volatile("ld.acquire.gpu.s32 %0, [%1];" : "=r"(v) : "l"(p) : "memory");
    return v;
}

__device__ __forceinline__ float warp_sum(float v) {
#pragma unroll
    for (int s = 16; s > 0; s >>= 1) v += __shfl_xor_sync(0xffffffffu, v, s);
    return v;
}

// ---------------------------------------------------------------------------
// ONE fused kernel, block roles by blockIdx:
//   [0,1024)      norm (8 rows, warp-per-row) -> g_zq, g_vpart
//   [1024,3104)   den (upper-triangle fp8 MMA tile) -> g_den, g_pospart
//   [3104,3168)   logden (per 128-row tile)        -> g_logpart
//   [3168,3296)   vpart level-1 (16 chunks each)   -> g_vpart2
//   [3296,3300)   group counts                      -> g_counts
//   last reduce-role arriver: final scalar + counter resets.
// ---------------------------------------------------------------------------
#define TILEB 32768
#define SM_TOTAL 69632

__global__ __launch_bounds__(256, 3) void fused_kernel(const float* __restrict__ zi,
                                                       const float* __restrict__ zj,
                                                       const long long* __restrict__ sf,
                                                       float* __restrict__ out) {
    extern __shared__ __align__(1024) unsigned char smem[];
    const int b = blockIdx.x;
    const int tid = threadIdx.x, wid = tid >> 5, lane = tid & 31;

    if (b < NORMBLK) {
        // ----------------- NORM ROLE -----------------
        float* szn = (float*)smem;                 // [8][DIMS]
        int*   sg  = (int*)(smem + 8 * DIMS * 4);  // [8]
        const int nb  = b;
        const int row = nb * 8 + wid;
        const float* src = (row < BHALF) ? (zi + (size_t)row * DIMS)
                                         : (zj + (size_t)(row - BHALF) * DIMS);
        float4 v0 = ((const float4*)src)[lane];
        float4 v1 = ((const float4*)src)[lane + 32];
        float ss = v0.x*v0.x + v0.y*v0.y + v0.z*v0.z + v0.w*v0.w
                 + v1.x*v1.x + v1.y*v1.y + v1.z*v1.z + v1.w*v1.w;
        ss = warp_sum(ss);
        float inv = (ss > 1e-16f) ? rsqrtf(ss) : 1e8f;
        v0.x *= inv; v0.y *= inv; v0.z *= inv; v0.w *= inv;
        v1.x *= inv; v1.y *= inv; v1.z *= inv; v1.w *= inv;
        ((float4*)&szn[wid * DIMS])[lane]      = v0;
        ((float4*)&szn[wid * DIMS])[lane + 32] = v1;

        unsigned short p01, p23;
        unsigned w;
        int tile = row >> 7, r = row & 127;
        unsigned rowbase = (unsigned)tile * 32768u + (unsigned)r * 256u;
        unsigned rx = (unsigned)(r & 7) << 4;

        asm("cvt.rn.satfinite.e4m3x2.f32 %0, %1, %2;" : "=h"(p01) : "f"(v0.y*QSCALE), "f"(v0.x*QSCALE));
        asm("cvt.rn.satfinite.e4m3x2.f32 %0, %1, %2;" : "=h"(p23) : "f"(v0.w*QSCALE), "f"(v0.z*QSCALE));
        asm("mov.b32 %0, {%1, %2};" : "=r"(w) : "h"(p01), "h"(p23));
        {
            unsigned byteoff = (unsigned)lane * 4u;
            unsigned c = byteoff >> 4, o = byteoff & 15u;
            *(unsigned*)(g_zq + rowbase + (((c << 4) ^ rx)) + o) = w;
        }
        asm("cvt.rn.satfinite.e4m3x2.f32 %0, %1, %2;" : "=h"(p01) : "f"(v1.y*QSCALE), "f"(v1.x*QSCALE));
        asm("cvt.rn.satfinite.e4m3x2.f32 %0, %1, %2;" : "=h"(p23) : "f"(v1.w*QSCALE), "f"(v1.z*QSCALE));
        asm("mov.b32 %0, {%1, %2};" : "=r"(w) : "h"(p01), "h"(p23));
        {
            unsigned byteoff = 128u + (unsigned)lane * 4u;
            unsigned c = byteoff >> 4, o = byteoff & 15u;
            *(unsigned*)(g_zq + rowbase + (((c << 4) ^ rx)) + o) = w;
        }

        if (nb < GBLK) {
            if (tid < 8) sg[tid] = (int)sf[nb * 8 + tid];
            __syncthreads();
            int t = tid;
            float a0 = 0.f, a1 = 0.f, a2 = 0.f, a3 = 0.f;
#pragma unroll
            for (int rr = 0; rr < 8; rr++) {
                float v = szn[rr * DIMS + t];
                int gg = sg[rr];
                a0 += (gg == 0) ? v : 0.f;
                a1 += (gg == 1) ? v : 0.f;
                a2 += (gg == 2) ? v : 0.f;
                a3 += (gg == 3) ? v : 0.f;
            }
            g_vpart[(0 * GBLK + nb) * DIMS + t] = a0;
            g_vpart[(1 * GBLK + nb) * DIMS + t] = a1;
            g_vpart[(2 * GBLK + nb) * DIMS + t] = a2;
            g_vpart[(3 * GBLK + nb) * DIMS + t] = a3;
        }

        __syncthreads();
        if (tid == 0) {
            __threadfence();
            atomicAdd(&g_tile_ready[nb >> 4], 1);
            atomicAdd(&g_normdone, 1);
        }
        return;
    }

    if (b < LOGBASE) {
        // ----------------- DEN ROLE -----------------
        const unsigned sb = smem_u32(smem);
        float* scol  = (float*)(smem + 2 * TILEB);          // [2][4][64]
        float* srow  = (float*)(smem + 2 * TILEB + 2048);   // [2][128]
        float* sposs = (float*)(smem + 2 * TILEB + 3072);   // [8]
        const int g = lane >> 2, tig = lane & 3;
        const int warpRi = wid >> 1;
        const int warpR  = warpRi * 32;
        const int warpC  = (wid & 1) * 64;

        int rem = b - NORMBLK, rt = 0;
        while (rem >= 64 - rt) { rem -= 64 - rt; rt++; }
        const int ct = rt + rem;
        const bool isDiag = (rt == ct);
        const bool isPos  = (ct == rt + 32);

        if (tid == 0) {
            while (ld_acquire(&g_tile_ready[rt]) < 16) { }
            if (!isDiag) while (ld_acquire(&g_tile_ready[ct]) < 16) { }
        }
        __syncthreads();

        {
            const unsigned char* As = g_zq + (size_t)rt * TILEB;
            const unsigned char* Bs = g_zq + (size_t)ct * TILEB;
#pragma unroll
            for (int i = 0; i < 8; i++) {
                unsigned o = i * 4096 + tid * 16;
                cp16(sb + o, As + o);
                if (!isDiag) cp16(sb + TILEB + o, Bs + o);
            }
            CP_COMMIT();
        }
        const unsigned sB = isDiag ? sb : (sb + TILEB);

        const int t4 = lane >> 3;
        const int rr = lane & 7;
        const unsigned hiA = (unsigned)(lane >> 4);
        const unsigned hiB = (unsigned)((lane >> 3) & 1);
        unsigned aBase[2], bBase[4];
#pragma unroll
        for (int mt = 0; mt < 2; mt++) {
            int arow = warpR + mt * 16 + ((t4 & 1) << 3) + rr;
            aBase[mt] = (unsigned)arow * 256u;
        }
#pragma unroll
        for (int q = 0; q < 4; q++) {
            int nrow = warpC + (q * 2 + (t4 >> 1)) * 8 + rr;
            bBase[q] = (unsigned)nrow * 256u;
        }

        float rs[2][2] = {{0.f, 0.f}, {0.f, 0.f}};
        float pacc = 0.f;

        CP_WAIT(0);
        __syncthreads();

#pragma unroll
        for (int pass = 0; pass < 2; pass++) {
            float acc[2][4][4];
#pragma unroll
            for (int mt = 0; mt < 2; mt++)
#pragma unroll
                for (int nt = 0; nt < 4; nt++)
#pragma unroll
                    for (int qq = 0; qq < 4; qq++) acc[mt][nt][qq] = 0.f;

#pragma unroll
            for (int ks = 0; ks < 8; ks++) {
                unsigned ca = ((2u * ks + hiA) ^ (unsigned)rr) << 4;
                unsigned cb = ((2u * ks + hiB) ^ (unsigned)rr) << 4;
                unsigned a[2][4];
                LDSM4(a[0][0], a[0][1], a[0][2], a[0][3], sb + aBase[0] + ca);
                LDSM4(a[1][0], a[1][1], a[1][2], a[1][3], sb + aBase[1] + ca);
                unsigned bb2[2][4];
                LDSM4(bb2[0][0], bb2[0][1], bb2[0][2], bb2[0][3], sB + bBase[2 * pass] + cb);
                LDSM4(bb2[1][0], bb2[1][1], bb2[1][2], bb2[1][3], sB + bBase[2 * pass + 1] + cb);
#pragma unroll
                for (int mt = 0; mt < 2; mt++)
#pragma unroll
                    for (int nt = 0; nt < 4; nt++)
                        MMAFP8(acc[mt][nt], a[mt], bb2[nt >> 1][(nt & 1) * 2], bb2[nt >> 1][(nt & 1) * 2 + 1]);
            }

            float cs[4][2];
#pragma unroll
            for (int nt = 0; nt < 4; nt++) { cs[nt][0] = 0.f; cs[nt][1] = 0.f; }

#pragma unroll
            for (int mt = 0; mt < 2; mt++) {
#pragma unroll
                for (int nt = 0; nt < 4; nt++) {
                    if (isDiag || isPos) {
                        int r0 = warpR + mt * 16 + g;
                        int cc = warpC + (4 * pass + nt) * 8 + tig * 2;
                        bool d00 = (r0 == cc), d01 = (r0 == cc + 1);
                        bool d10 = (r0 + 8 == cc), d11 = (r0 + 8 == cc + 1);
                        if (isPos) {
                            if (d00) pacc += acc[mt][nt][0];
                            if (d01) pacc += acc[mt][nt][1];
                            if (d10) pacc += acc[mt][nt][2];
                            if (d11) pacc += acc[mt][nt][3];
                        }
                        float e0 = fexp2q(acc[mt][nt][0]);
                        float e1 = fexp2q(acc[mt][nt][1]);
                        float e2 = fexp2q(acc[mt][nt][2]);
                        float e3 = fexp2q(acc[mt][nt][3]);
                        if (isDiag) {
                            if (d00) e0 = 0.f;
                            if (d01) e1 = 0.f;
                            if (d10) e2 = 0.f;
                            if (d11) e3 = 0.f;
                        } else {
                            cs[nt][0] += e0 + e2;
                            cs[nt][1] += e1 + e3;
                        }
                        rs[mt][0] += e0 + e1;
                        rs[mt][1] += e2 + e3;
                    } else {
                        float e0 = fexp2q(acc[mt][nt][0]);
                        float e1 = fexp2q(acc[mt][nt][1]);
                        float e2 = fexp2q(acc[mt][nt][2]);
                        float e3 = fexp2q(acc[mt][nt][3]);
                        cs[nt][0] += e0 + e2;
                        cs[nt][1] += e1 + e3;
                        rs[mt][0] += e0 + e1;
                        rs[mt][1] += e2 + e3;
                    }
                }
            }

            if (!isDiag) {
#pragma unroll
                for (int nt = 0; nt < 4; nt++) {
#pragma unroll
                    for (int jj = 0; jj < 2; jj++) {
                        float v = cs[nt][jj];
                        v += __shfl_xor_sync(0xffffffffu, v, 4);
                        v += __shfl_xor_sync(0xffffffffu, v, 8);
                        v += __shfl_xor_sync(0xffffffffu, v, 16);
                        if (lane < 4) {
                            int e = (wid & 1) * 32 + nt * 8 + lane * 2 + jj;
                            scol[pass * 256 + warpRi * 64 + e] = v;
                        }
                    }
                }
            }
        }

        {
#pragma unroll
            for (int mt = 0; mt < 2; mt++)
#pragma unroll
                for (int h = 0; h < 2; h++) {
                    float v = rs[mt][h];
                    v += __shfl_xor_sync(0xffffffffu, v, 1);
                    v += __shfl_xor_sync(0xffffffffu, v, 2);
                    if (tig == 0)
                        srow[(wid & 1) * 128 + warpR + mt * 16 + h * 8 + g] = v;
                }
        }
        if (isPos) {
            pacc = warp_sum(pacc);
            if (lane == 0) sposs[wid] = pacc;
        }

        __syncthreads();

        if (wid < 2) {
            if (!isDiag) {
#pragma unroll
                for (int pass = 0; pass < 2; pass++) {
                    int e = wid * 32 + lane;
                    int half = e >> 5, cwi = e & 31;
                    int col = half * 64 + 32 * pass + cwi;
                    const float* sc = scol + pass * 256;
                    float v = ((sc[0 * 64 + e] + sc[1 * 64 + e])
                             + (sc[2 * 64 + e] + sc[3 * 64 + e]));
                    g_den[(size_t)rt * NTOT + ct * 128 + col] = v;
                }
            }
        } else if (wid < 4) {
            int base = (wid - 2) * 64;
#pragma unroll
            for (int k = 0; k < 2; k++) {
                int r = base + lane + k * 32;
                float v = srow[r] + srow[128 + r];
                g_den[(size_t)ct * NTOT + rt * 128 + r] = v;
            }
        } else if (wid == 4 && isPos && lane == 0) {
            float s = ((sposs[0] + sposs[1]) + (sposs[2] + sposs[3]))
                    + ((sposs[4] + sposs[5]) + (sposs[6] + sposs[7]));
            g_pospart[rt] = s;
        }

        __syncthreads();
        if (tid == 0) {
            __threadfence();
            atomicAdd(&g_dentile[rt], 1);
            if (!isDiag) atomicAdd(&g_dentile[ct], 1);
            int old = atomicAdd(&g_denarrive, 1);
            if (old == DENBLK - 1) {
#pragma unroll
                for (int i = 0; i < 64; i++) g_tile_ready[i] = 0;
                g_denarrive = 0;
            }
        }
        return;
    }

    // ----------------- REDUCE ROLES -----------------
    if (b < VPBASE) {
        // logden for tile b2
        const int b2 = b - LOGBASE;
        if (tid == 0) while (ld_acquire(&g_dentile[b2]) < 64) { }
        __syncthreads();
        float* part = (float*)smem;            // [2][128]
        float* red  = (float*)(smem + 1024);   // [128]
        const int rl = tid & 127, chunk = tid >> 7;
        float p = 0.f;
#pragma unroll 8
        for (int s = chunk; s < 64; s += 2)
            p += g_den[(size_t)s * NTOT + b2 * 128 + rl];
        part[chunk * 128 + rl] = p;
        __syncthreads();
        if (chunk == 0) red[rl] = logf(part[rl] + part[128 + rl]);
        __syncthreads();
        for (int s = 64; s > 0; s >>= 1) {
            if (tid < s) red[tid] += red[tid + s];
            __syncthreads();
        }
        if (tid == 0) g_logpart[b2] = red[0];
    } else if (b < CNTBASE) {
        // vpart level-1: (group, 16-chunk segment)
        const int bb = b - VPBASE;            // 0..127
        const int gg = bb >> 5, seg = bb & 31;
        if (tid == 0) while (ld_acquire(&g_normdone) < NORMBLK) { }
        __syncthreads();
        if (tid < DIMS) {
            float v = 0.f;
#pragma unroll
            for (int ch = seg * 16; ch < seg * 16 + 16; ch++)
                v += g_vpart[(gg * GBLK + ch) * DIMS + tid];
            g_vpart2[(gg * 32 + seg) * DIMS + tid] = v;
        }
    } else {
        // counts (inputs only, no wait)
        const int gg = b - CNTBASE;
        int* redi = (int*)smem;               // [256]
        int c = 0;
        for (int r = tid; r < BHALF; r += 256)
            c += ((int)sf[r] == gg);
        redi[tid] = c;
        __syncthreads();
        for (int s = 128; s > 0; s >>= 1) {
            if (tid < s) redi[tid] += redi[tid + s];
            __syncthreads();
        }
        if (tid == 0) g_counts[gg] = redi[0];
    }

    // Last reduce-role arriver assembles the final scalar.
    __syncthreads();
    int* slast = (int*)(smem + 5632);
    if (tid == 0) {
        __threadfence();
        int old = atomicAdd(&g_arrive, 1);
        *slast = (old == NRED - 1) ? 1 : 0;
    }
    __syncthreads();
    if (!*slast) return;
    __threadfence();

    float* red2  = (float*)(smem + 4096);   // [256]
    float* sgsum = (float*)(smem + 5120);   // [4]

    for (int gg = 0; gg < NGROUP; gg++) {
        {
            float v = 0.f;
#pragma unroll
            for (int seg = 0; seg < 32; seg++)
                v += g_vpart2[(gg * 32 + seg) * DIMS + tid];
            red2[tid] = v * v;
        }
        __syncthreads();
        for (int s = 128; s > 0; s >>= 1) {
            if (tid < s) red2[tid] += red2[tid + s];
            __syncthreads();
        }
        if (tid == 0) sgsum[gg] = red2[0];
        __syncthreads();
    }

    {
        float v = (tid < 64) ? g_logpart[tid] : 0.f;
        if (tid < 32) v += g_pospart[tid] * (-0.0625f);
        red2[tid] = v;
    }
    __syncthreads();
    for (int s = 128; s > 0; s >>= 1) {
        if (tid < s) red2[tid] += red2[tid + s];
        __syncthreads();
    }

    if (tid < 64) g_dentile[tid] = 0;       // reset for next replay
    if (tid == 0) {
        float contrastive = red2[0] / (float)NTOT;
        float fair_acc = 0.f, nuniq = 0.f;
        for (int gg = 0; gg < NGROUP; gg++) {
            float c = (float)g_counts[gg];
            if (c > 0.f) nuniq += 1.f;
            if (c > 1.f) fair_acc += sgsum[gg] / (c * (c - 1.f));
        }
        float fairness = 0.1f * (fair_acc / fmaxf(nuniq, 1.f));
        out[0] = contrastive + fairness;
        g_normdone = 0;
        g_arrive = 0;
    }
}

// ---------------------------------------------------------------------------
extern "C" void kernel_launch(void* const* d_in, const int* in_sizes, int n_in,
                              void* d_out, int out_size) {
    const float*     zi  = (const float*)d_in[0];
    const float*     zj  = (const float*)d_in[1];
    const long long* sf  = (const long long*)d_in[2];
    float*           out = (float*)d_out;

    cudaFuncSetAttribute(fused_kernel, cudaFuncAttributeMaxDynamicSharedMemorySize, SM_TOTAL);

    fused_kernel<<<NBLK_ALL, 256, SM_TOTAL>>>(zi, zj, sf, out);
}

// round 16
// speedup vs baseline: 1.3960x; 1.3960x over previous
#include <cuda_runtime.h>

// Problem constants (fixed by setup_inputs)
#define BHALF  4096
#define NTOT   8192
#define DIMS   256
#define NSLOT  64
#define NGROUP 4
#define GBLK   512          // 8-row norm chunks over first half

// fp8 quantization: zn * 8 -> e4m3.  S_fp8 = 64*S.  exp(2S) = exp2(S_fp8*(2/ln2)/64)
#define QSCALE   8.0f
#define EXP2K    0.04508422002778011f

#define NORMBLK  1024       // 8 rows each
#define DENBLK   2080
#define NBLK_ALL (NORMBLK + DENBLK)

// ---------------------------------------------------------------------------
// Scratch (device globals; no allocations allowed)
// ---------------------------------------------------------------------------
__device__ __align__(1024) unsigned char g_zq[(size_t)NTOT * DIMS];  // e4m3*8, swizzled tiles (2 MB)
__device__ float g_den[(size_t)NSLOT * NTOT];                        // slot-major, 2 MB
__device__ float g_pospart[32];
__device__ float g_vpart[NGROUP * GBLK * DIMS];
__device__ float g_vpart2[NGROUP * 32 * DIMS];
__device__ float g_logpart[64];
__device__ int   g_counts[NGROUP];
__device__ int   g_tile_ready[64];   // norm -> den (16 arrivals per tile)
__device__ int   g_denarrive = 0;
__device__ int   g_arrive = 0;

// ---------------------------------------------------------------------------
// PTX helpers (family-portable: cp.async, ldmatrix, mma.sync fp8, ex2.approx)
// ---------------------------------------------------------------------------
__device__ __forceinline__ unsigned smem_u32(const void* p) {
    unsigned a;
    asm("{ .reg .u64 t; cvta.to.shared.u64 t, %1; cvt.u32.u64 %0, t; }" : "=r"(a) : "l"(p));
    return a;
}
__device__ __forceinline__ void cp16(unsigned dst, const void* src) {
    asm volatile("cp.async.cg.shared.global [%0], [%1], 16;" :: "r"(dst), "l"(src) : "memory");
}
#define CP_COMMIT() asm volatile("cp.async.commit_group;" ::: "memory")
#define CP_WAIT(n)  asm volatile("cp.async.wait_group %0;" :: "n"(n) : "memory")

#define LDSM4(r0, r1, r2, r3, a)                                              \
    asm volatile("ldmatrix.sync.aligned.m8n8.x4.shared.b16 {%0,%1,%2,%3}, [%4];" \
                 : "=r"(r0), "=r"(r1), "=r"(r2), "=r"(r3) : "r"(a))

#define MMAFP8(d, a, b0, b1)                                                  \
    asm volatile("mma.sync.aligned.m16n8k32.row.col.f32.e4m3.e4m3.f32 "       \
                 "{%0,%1,%2,%3}, {%4,%5,%6,%7}, {%8,%9}, {%0,%1,%2,%3};"      \
                 : "+f"((d)[0]), "+f"((d)[1]), "+f"((d)[2]), "+f"((d)[3])     \
                 : "r"((a)[0]), "r"((a)[1]), "r"((a)[2]), "r"((a)[3]),        \
                   "r"(b0), "r"(b1))

__device__ __forceinline__ float fexp2q(float s) {
    float r;
    asm("ex2.approx.f32 %0, %1;" : "=f"(r) : "f"(s * EXP2K));
    return r;
}

__device__ __forceinline__ int ld_acquire(const int* p) {
    int v;
    asm volatile("ld.acquire.gpu.s32 %0, [%1];" : "=r"(v) : "l"(p) : "memory");
    return v;
}

__device__ __forceinline__ float warp_sum(float v) {
#pragma unroll
    for (int s = 16; s > 0; s >>= 1) v += __shfl_xor_sync(0xffffffffu, v, s);
    return v;
}

// ---------------------------------------------------------------------------
// Fused kernel: blocks [0,1024) = norm role (8 rows each, warp-per-row);
// blocks [1024, 3104) = den role (upper-triangle tile, fp8 MMA).
// Tile readiness via g_tile_ready (16 norm arrivals per 128-row tile).
// Den waits only depend on EARLIER-issued blocks -> no residency trap.
// ---------------------------------------------------------------------------
#define TILEB 32768
#define SM_TOTAL 69632

__global__ __launch_bounds__(256, 3) void fused_kernel(const float* __restrict__ zi,
                                                       const float* __restrict__ zj,
                                                       const long long* __restrict__ sf) {
    extern __shared__ __align__(1024) unsigned char smem[];
    const int tid = threadIdx.x, wid = tid >> 5, lane = tid & 31;

    if ((int)blockIdx.x < NORMBLK) {
        // ----------------- NORM ROLE -----------------
        float* szn = (float*)smem;                 // [8][DIMS]
        int*   sg  = (int*)(smem + 8 * DIMS * 4);  // [8]
        const int nb  = blockIdx.x;
        const int row = nb * 8 + wid;
        const float* src = (row < BHALF) ? (zi + (size_t)row * DIMS)
                                         : (zj + (size_t)(row - BHALF) * DIMS);
        float4 v0 = ((const float4*)src)[lane];
        float4 v1 = ((const float4*)src)[lane + 32];
        float ss = v0.x*v0.x + v0.y*v0.y + v0.z*v0.z + v0.w*v0.w
                 + v1.x*v1.x + v1.y*v1.y + v1.z*v1.z + v1.w*v1.w;
        ss = warp_sum(ss);
        float inv = (ss > 1e-16f) ? rsqrtf(ss) : 1e8f;
        v0.x *= inv; v0.y *= inv; v0.z *= inv; v0.w *= inv;
        v1.x *= inv; v1.y *= inv; v1.z *= inv; v1.w *= inv;
        ((float4*)&szn[wid * DIMS])[lane]      = v0;
        ((float4*)&szn[wid * DIMS])[lane + 32] = v1;

        unsigned short p01, p23;
        unsigned w;
        int tile = row >> 7, r = row & 127;
        unsigned rowbase = (unsigned)tile * 32768u + (unsigned)r * 256u;
        unsigned rx = (unsigned)(r & 7) << 4;

        asm("cvt.rn.satfinite.e4m3x2.f32 %0, %1, %2;" : "=h"(p01) : "f"(v0.y*QSCALE), "f"(v0.x*QSCALE));
        asm("cvt.rn.satfinite.e4m3x2.f32 %0, %1, %2;" : "=h"(p23) : "f"(v0.w*QSCALE), "f"(v0.z*QSCALE));
        asm("mov.b32 %0, {%1, %2};" : "=r"(w) : "h"(p01), "h"(p23));
        {
            unsigned byteoff = (unsigned)lane * 4u;
            unsigned c = byteoff >> 4, o = byteoff & 15u;
            *(unsigned*)(g_zq + rowbase + (((c << 4) ^ rx)) + o) = w;
        }
        asm("cvt.rn.satfinite.e4m3x2.f32 %0, %1, %2;" : "=h"(p01) : "f"(v1.y*QSCALE), "f"(v1.x*QSCALE));
        asm("cvt.rn.satfinite.e4m3x2.f32 %0, %1, %2;" : "=h"(p23) : "f"(v1.w*QSCALE), "f"(v1.z*QSCALE));
        asm("mov.b32 %0, {%1, %2};" : "=r"(w) : "h"(p01), "h"(p23));
        {
            unsigned byteoff = 128u + (unsigned)lane * 4u;
            unsigned c = byteoff >> 4, o = byteoff & 15u;
            *(unsigned*)(g_zq + rowbase + (((c << 4) ^ rx)) + o) = w;
        }

        // Group partials (first half rows)
        if (nb < GBLK) {
            if (tid < 8) sg[tid] = (int)sf[nb * 8 + tid];
            __syncthreads();
            int t = tid;
            float a0 = 0.f, a1 = 0.f, a2 = 0.f, a3 = 0.f;
#pragma unroll
            for (int rr = 0; rr < 8; rr++) {
                float v = szn[rr * DIMS + t];
                int gg = sg[rr];
                a0 += (gg == 0) ? v : 0.f;
                a1 += (gg == 1) ? v : 0.f;
                a2 += (gg == 2) ? v : 0.f;
                a3 += (gg == 3) ? v : 0.f;
            }
            g_vpart[(0 * GBLK + nb) * DIMS + t] = a0;
            g_vpart[(1 * GBLK + nb) * DIMS + t] = a1;
            g_vpart[(2 * GBLK + nb) * DIMS + t] = a2;
            g_vpart[(3 * GBLK + nb) * DIMS + t] = a3;
        }

        __syncthreads();
        if (tid == 0) {
            __threadfence();
            atomicAdd(&g_tile_ready[nb >> 4], 1);
        }
        return;
    }

    // ----------------- DEN ROLE -----------------
    const unsigned sb = smem_u32(smem);
    float* scol  = (float*)(smem + 2 * TILEB);          // [2][4][64] (per pass)
    float* srow  = (float*)(smem + 2 * TILEB + 2048);   // [2][128]
    float* sposs = (float*)(smem + 2 * TILEB + 3072);   // [8]
    const int g = lane >> 2, tig = lane & 3;
    const int warpRi = wid >> 1;
    const int warpR  = warpRi * 32;
    const int warpC  = (wid & 1) * 64;

    int rem = blockIdx.x - NORMBLK, rt = 0;
    while (rem >= 64 - rt) { rem -= 64 - rt; rt++; }
    const int ct = rt + rem;
    const bool isDiag = (rt == ct);
    const bool isPos  = (ct == rt + 32);

    if (tid == 0) {
        while (ld_acquire(&g_tile_ready[rt]) < 16) { }
        if (!isDiag) while (ld_acquire(&g_tile_ready[ct]) < 16) { }
    }
    __syncthreads();

    {
        const unsigned char* As = g_zq + (size_t)rt * TILEB;
        const unsigned char* Bs = g_zq + (size_t)ct * TILEB;
#pragma unroll
        for (int i = 0; i < 8; i++) {
            unsigned o = i * 4096 + tid * 16;
            cp16(sb + o, As + o);
            if (!isDiag) cp16(sb + TILEB + o, Bs + o);
        }
        CP_COMMIT();
    }
    const unsigned sB = isDiag ? sb : (sb + TILEB);

    const int t4 = lane >> 3;
    const int rr = lane & 7;
    const unsigned hiA = (unsigned)(lane >> 4);
    const unsigned hiB = (unsigned)((lane >> 3) & 1);
    unsigned aBase[2], bBase[4];
#pragma unroll
    for (int mt = 0; mt < 2; mt++) {
        int arow = warpR + mt * 16 + ((t4 & 1) << 3) + rr;
        aBase[mt] = (unsigned)arow * 256u;
    }
#pragma unroll
    for (int q = 0; q < 4; q++) {
        int nrow = warpC + (q * 2 + (t4 >> 1)) * 8 + rr;
        bBase[q] = (unsigned)nrow * 256u;
    }

    float rs[2][2] = {{0.f, 0.f}, {0.f, 0.f}};
    float pacc = 0.f;

    CP_WAIT(0);
    __syncthreads();

#pragma unroll
    for (int pass = 0; pass < 2; pass++) {
        float acc[2][4][4];
#pragma unroll
        for (int mt = 0; mt < 2; mt++)
#pragma unroll
            for (int nt = 0; nt < 4; nt++)
#pragma unroll
                for (int qq = 0; qq < 4; qq++) acc[mt][nt][qq] = 0.f;

#pragma unroll
        for (int ks = 0; ks < 8; ks++) {
            unsigned ca = ((2u * ks + hiA) ^ (unsigned)rr) << 4;
            unsigned cb = ((2u * ks + hiB) ^ (unsigned)rr) << 4;
            unsigned a[2][4];
            LDSM4(a[0][0], a[0][1], a[0][2], a[0][3], sb + aBase[0] + ca);
            LDSM4(a[1][0], a[1][1], a[1][2], a[1][3], sb + aBase[1] + ca);
            unsigned bb2[2][4];
            LDSM4(bb2[0][0], bb2[0][1], bb2[0][2], bb2[0][3], sB + bBase[2 * pass] + cb);
            LDSM4(bb2[1][0], bb2[1][1], bb2[1][2], bb2[1][3], sB + bBase[2 * pass + 1] + cb);
#pragma unroll
            for (int mt = 0; mt < 2; mt++)
#pragma unroll
                for (int nt = 0; nt < 4; nt++)
                    MMAFP8(acc[mt][nt], a[mt], bb2[nt >> 1][(nt & 1) * 2], bb2[nt >> 1][(nt & 1) * 2 + 1]);
        }

        float cs[4][2];
#pragma unroll
        for (int nt = 0; nt < 4; nt++) { cs[nt][0] = 0.f; cs[nt][1] = 0.f; }

#pragma unroll
        for (int mt = 0; mt < 2; mt++) {
#pragma unroll
            for (int nt = 0; nt < 4; nt++) {
                if (isDiag || isPos) {
                    int r0 = warpR + mt * 16 + g;
                    int cc = warpC + (4 * pass + nt) * 8 + tig * 2;
                    bool d00 = (r0 == cc), d01 = (r0 == cc + 1);
                    bool d10 = (r0 + 8 == cc), d11 = (r0 + 8 == cc + 1);
                    if (isPos) {
                        if (d00) pacc += acc[mt][nt][0];
                        if (d01) pacc += acc[mt][nt][1];
                        if (d10) pacc += acc[mt][nt][2];
                        if (d11) pacc += acc[mt][nt][3];
                    }
                    float e0 = fexp2q(acc[mt][nt][0]);
                    float e1 = fexp2q(acc[mt][nt][1]);
                    float e2 = fexp2q(acc[mt][nt][2]);
                    float e3 = fexp2q(acc[mt][nt][3]);
                    if (isDiag) {
                        if (d00) e0 = 0.f;
                        if (d01) e1 = 0.f;
                        if (d10) e2 = 0.f;
                        if (d11) e3 = 0.f;
                    } else {
                        cs[nt][0] += e0 + e2;
                        cs[nt][1] += e1 + e3;
                    }
                    rs[mt][0] += e0 + e1;
                    rs[mt][1] += e2 + e3;
                } else {
                    float e0 = fexp2q(acc[mt][nt][0]);
                    float e1 = fexp2q(acc[mt][nt][1]);
                    float e2 = fexp2q(acc[mt][nt][2]);
                    float e3 = fexp2q(acc[mt][nt][3]);
                    cs[nt][0] += e0 + e2;
                    cs[nt][1] += e1 + e3;
                    rs[mt][0] += e0 + e1;
                    rs[mt][1] += e2 + e3;
                }
            }
        }

        if (!isDiag) {
#pragma unroll
            for (int nt = 0; nt < 4; nt++) {
#pragma unroll
                for (int jj = 0; jj < 2; jj++) {
                    float v = cs[nt][jj];
                    v += __shfl_xor_sync(0xffffffffu, v, 4);
                    v += __shfl_xor_sync(0xffffffffu, v, 8);
                    v += __shfl_xor_sync(0xffffffffu, v, 16);
                    if (lane < 4) {
                        int e = (wid & 1) * 32 + nt * 8 + lane * 2 + jj;
                        scol[pass * 256 + warpRi * 64 + e] = v;
                    }
                }
            }
        }
    }

    {
#pragma unroll
        for (int mt = 0; mt < 2; mt++)
#pragma unroll
            for (int h = 0; h < 2; h++) {
                float v = rs[mt][h];
                v += __shfl_xor_sync(0xffffffffu, v, 1);
                v += __shfl_xor_sync(0xffffffffu, v, 2);
                if (tig == 0)
                    srow[(wid & 1) * 128 + warpR + mt * 16 + h * 8 + g] = v;
            }
    }
    if (isPos) {
        pacc = warp_sum(pacc);
        if (lane == 0) sposs[wid] = pacc;
    }

    __syncthreads();

    if (wid < 2) {
        if (!isDiag) {
#pragma unroll
            for (int pass = 0; pass < 2; pass++) {
                int e = wid * 32 + lane;
                int half = e >> 5, cwi = e & 31;
                int col = half * 64 + 32 * pass + cwi;
                const float* sc = scol + pass * 256;
                float v = ((sc[0 * 64 + e] + sc[1 * 64 + e])
                         + (sc[2 * 64 + e] + sc[3 * 64 + e]));
                g_den[(size_t)rt * NTOT + ct * 128 + col] = v;
            }
        }
    } else if (wid < 4) {
        int base = (wid - 2) * 64;
#pragma unroll
        for (int k = 0; k < 2; k++) {
            int r = base + lane + k * 32;
            float v = srow[r] + srow[128 + r];
            g_den[(size_t)ct * NTOT + rt * 128 + r] = v;
        }
    } else if (wid == 4 && isPos && lane == 0) {
        float s = ((sposs[0] + sposs[1]) + (sposs[2] + sposs[3]))
                + ((sposs[4] + sposs[5]) + (sposs[6] + sposs[7]));
        g_pospart[rt] = s;
    }

    __syncthreads();
    if (tid == 0) {
        int old = atomicAdd(&g_denarrive, 1);
        if (old == DENBLK - 1) {
#pragma unroll
            for (int i = 0; i < 64; i++) g_tile_ready[i] = 0;
            g_denarrive = 0;
        }
    }
}

// ---------------------------------------------------------------------------
// Reduce kernel, grid = 196 blocks x 512:
//   b<64: logden tile; b<192: vpart level-1 (16 chunks each); b<196: counts.
//   Last-arriving block assembles the final scalar.
// ---------------------------------------------------------------------------
#define NRED 196

__global__ __launch_bounds__(512) void reduce_kernel(const long long* __restrict__ sf,
                                                     float* __restrict__ out) {
    const int b = blockIdx.x;
    const int t = threadIdx.x;
    __shared__ float part[4][128];
    __shared__ float red[128];
    __shared__ int   redi[512];
    __shared__ float red2[256];
    __shared__ float sgsum[NGROUP];
    __shared__ int   slast;

    if (b < 64) {
        const int rl    = t & 127;
        const int chunk = t >> 7;
        const int row   = b * 128 + rl;
        float p = 0.f;
#pragma unroll
        for (int s = 0; s < 16; s++)
            p += g_den[(size_t)(4 * s + chunk) * NTOT + row];
        part[chunk][rl] = p;
        __syncthreads();
        if (chunk == 0) {
            float d = ((part[0][rl] + part[1][rl]) + (part[2][rl] + part[3][rl]));
            red[rl] = logf(d);
        }
        __syncthreads();
        for (int s = 64; s > 0; s >>= 1) {
            if (t < s) red[t] += red[t + s];
            __syncthreads();
        }
        if (t == 0) g_logpart[b] = red[0];
    } else if (b < 192) {
        const int bb = b - 64;                // 0..127
        const int gg = bb >> 5, seg = bb & 31;
        if (t < DIMS) {
            float v = 0.f;
#pragma unroll
            for (int ch = seg * 16; ch < seg * 16 + 16; ch++)
                v += g_vpart[(gg * GBLK + ch) * DIMS + t];
            g_vpart2[(gg * 32 + seg) * DIMS + t] = v;
        }
    } else {
        const int gg = b - 192;
        int c = 0;
#pragma unroll
        for (int r = t; r < BHALF; r += 512)
            c += ((int)sf[r] == gg);
        redi[t] = c;
        __syncthreads();
        for (int s = 256; s > 0; s >>= 1) {
            if (t < s) redi[t] += redi[t + s];
            __syncthreads();
        }
        if (t == 0) g_counts[gg] = redi[0];
    }

    __syncthreads();
    if (t == 0) {
        __threadfence();
        int old = atomicAdd(&g_arrive, 1);
        slast = (old == NRED - 1) ? 1 : 0;
    }
    __syncthreads();
    if (!slast) return;
    __threadfence();

    for (int gg = 0; gg < NGROUP; gg++) {
        if (t < 256) {
            float v = 0.f;
#pragma unroll
            for (int seg = 0; seg < 32; seg++)
                v += g_vpart2[(gg * 32 + seg) * DIMS + t];
            red2[t] = v * v;
        }
        __syncthreads();
        for (int s = 128; s > 0; s >>= 1) {
            if (t < s) red2[t] += red2[t + s];
            __syncthreads();
        }
        if (t == 0) sgsum[gg] = red2[0];
        __syncthreads();
    }

    if (t < 256) {
        float v = (t < 64) ? g_logpart[t] : 0.f;
        if (t < 32) v += g_pospart[t] * (-0.0625f);
        red2[t] = v;
    }
    __syncthreads();
    for (int s = 128; s > 0; s >>= 1) {
        if (t < s) red2[t] += red2[t + s];
        __syncthreads();
    }

    if (t == 0) {
        float contrastive = red2[0] / (float)NTOT;
        float fair_acc = 0.f, nuniq = 0.f;
        for (int gg = 0; gg < NGROUP; gg++) {
            float c = (float)g_counts[gg];
            if (c > 0.f) nuniq += 1.f;
            if (c > 1.f) fair_acc += sgsum[gg] / (c * (c - 1.f));
        }
        float fairness = 0.1f * (fair_acc / fmaxf(nuniq, 1.f));
        out[0] = contrastive + fairness;
        g_arrive = 0;                     // reset for next graph replay
    }
}

// ---------------------------------------------------------------------------
extern "C" void kernel_launch(void* const* d_in, const int* in_sizes, int n_in,
                              void* d_out, int out_size) {
    const float*     zi  = (const float*)d_in[0];
    const float*     zj  = (const float*)d_in[1];
    const long long* sf  = (const long long*)d_in[2];
    float*           out = (float*)d_out;

    cudaFuncSetAttribute(fused_kernel, cudaFuncAttributeMaxDynamicSharedMemorySize, SM_TOTAL);

    fused_kernel<<<NBLK_ALL, 256, SM_TOTAL>>>(zi, zj, sf);
    reduce_kernel<<<NRED, 512>>>(sf, out);
}

// round 17
// speedup vs baseline: 1.4147x; 1.0134x over previous
#include <cuda_runtime.h>

// Problem constants (fixed by setup_inputs)
#define BHALF  4096
#define NTOT   8192
#define DIMS   256
#define NSLOT  64
#define NGROUP 4
#define GBLK   512          // 8-row norm chunks over first half

// fp8 quantization: zn * 8 -> e4m3.  S_fp8 = 64*S.  exp(2S) = exp2(S_fp8*(2/ln2)/64)
#define QSCALE   8.0f
#define EXP2K    0.04508422002778011f

#define NORMBLK  1024       // 8 rows each
#define DENBLK   2080
#define NBLK_ALL (NORMBLK + DENBLK)

// ---------------------------------------------------------------------------
// Scratch (device globals; no allocations allowed)
// ---------------------------------------------------------------------------
__device__ __align__(1024) unsigned char g_zq[(size_t)NTOT * DIMS];  // e4m3*8, swizzled tiles (2 MB)
__device__ float g_den[(size_t)NSLOT * NTOT];                        // slot-major, 2 MB
__device__ float g_pospart[32];
__device__ float g_vpart[NGROUP * GBLK * DIMS];
__device__ float g_vpart2[NGROUP * 32 * DIMS];
__device__ float g_logpart[128];
__device__ int   g_counts[NGROUP];
__device__ int   g_tile_ready[64];   // norm -> den (16 arrivals per tile)
__device__ int   g_denarrive = 0;
__device__ int   g_arrive = 0;

// ---------------------------------------------------------------------------
// PTX helpers (family-portable: cp.async, ldmatrix, mma.sync fp8, ex2.approx)
// ---------------------------------------------------------------------------
__device__ __forceinline__ unsigned smem_u32(const void* p) {
    unsigned a;
    asm("{ .reg .u64 t; cvta.to.shared.u64 t, %1; cvt.u32.u64 %0, t; }" : "=r"(a) : "l"(p));
    return a;
}
__device__ __forceinline__ void cp16(unsigned dst, const void* src) {
    asm volatile("cp.async.cg.shared.global [%0], [%1], 16;" :: "r"(dst), "l"(src) : "memory");
}
#define CP_COMMIT() asm volatile("cp.async.commit_group;" ::: "memory")
#define CP_WAIT(n)  asm volatile("cp.async.wait_group %0;" :: "n"(n) : "memory")

#define LDSM4(r0, r1, r2, r3, a)                                              \
    asm volatile("ldmatrix.sync.aligned.m8n8.x4.shared.b16 {%0,%1,%2,%3}, [%4];" \
                 : "=r"(r0), "=r"(r1), "=r"(r2), "=r"(r3) : "r"(a))

#define MMAFP8(d, a, b0, b1)                                                  \
    asm volatile("mma.sync.aligned.m16n8k32.row.col.f32.e4m3.e4m3.f32 "       \
                 "{%0,%1,%2,%3}, {%4,%5,%6,%7}, {%8,%9}, {%0,%1,%2,%3};"      \
                 : "+f"((d)[0]), "+f"((d)[1]), "+f"((d)[2]), "+f"((d)[3])     \
                 : "r"((a)[0]), "r"((a)[1]), "r"((a)[2]), "r"((a)[3]),        \
                   "r"(b0), "r"(b1))

__device__ __forceinline__ float fexp2q(float s) {
    float r;
    asm("ex2.approx.f32 %0, %1;" : "=f"(r) : "f"(s * EXP2K));
    return r;
}

__device__ __forceinline__ int ld_acquire(const int* p) {
    int v;
    asm volatile("ld.acquire.gpu.s32 %0, [%1];" : "=r"(v) : "l"(p) : "memory");
    return v;
}

__device__ __forceinline__ float warp_sum(float v) {
#pragma unroll
    for (int s = 16; s > 0; s >>= 1) v += __shfl_xor_sync(0xffffffffu, v, s);
    return v;
}

// ---------------------------------------------------------------------------
// Fused kernel: blocks [0,1024) = norm role (8 rows each, warp-per-row);
// blocks [1024, 3104) = den role (upper-triangle tile, fp8 MMA).
// Den waits only depend on EARLIER-issued blocks -> no residency trap.
// ---------------------------------------------------------------------------
#define TILEB 32768
#define SM_TOTAL 69632

__global__ __launch_bounds__(256, 3) void fused_kernel(const float* __restrict__ zi,
                                                       const float* __restrict__ zj,
                                                       const long long* __restrict__ sf) {
    extern __shared__ __align__(1024) unsigned char smem[];
    const int tid = threadIdx.x, wid = tid >> 5, lane = tid & 31;

    if ((int)blockIdx.x < NORMBLK) {
        // ----------------- NORM ROLE -----------------
        float* szn = (float*)smem;                 // [8][DIMS]
        int*   sg  = (int*)(smem + 8 * DIMS * 4);  // [8]
        const int nb  = blockIdx.x;
        const int row = nb * 8 + wid;
        const float* src = (row < BHALF) ? (zi + (size_t)row * DIMS)
                                         : (zj + (size_t)(row - BHALF) * DIMS);
        float4 v0 = ((const float4*)src)[lane];
        float4 v1 = ((const float4*)src)[lane + 32];
        float ss = v0.x*v0.x + v0.y*v0.y + v0.z*v0.z + v0.w*v0.w
                 + v1.x*v1.x + v1.y*v1.y + v1.z*v1.z + v1.w*v1.w;
        ss = warp_sum(ss);
        float inv = (ss > 1e-16f) ? rsqrtf(ss) : 1e8f;
        v0.x *= inv; v0.y *= inv; v0.z *= inv; v0.w *= inv;
        v1.x *= inv; v1.y *= inv; v1.z *= inv; v1.w *= inv;
        ((float4*)&szn[wid * DIMS])[lane]      = v0;
        ((float4*)&szn[wid * DIMS])[lane + 32] = v1;

        unsigned short p01, p23;
        unsigned w;
        int tile = row >> 7, r = row & 127;
        unsigned rowbase = (unsigned)tile * 32768u + (unsigned)r * 256u;
        unsigned rx = (unsigned)(r & 7) << 4;

        asm("cvt.rn.satfinite.e4m3x2.f32 %0, %1, %2;" : "=h"(p01) : "f"(v0.y*QSCALE), "f"(v0.x*QSCALE));
        asm("cvt.rn.satfinite.e4m3x2.f32 %0, %1, %2;" : "=h"(p23) : "f"(v0.w*QSCALE), "f"(v0.z*QSCALE));
        asm("mov.b32 %0, {%1, %2};" : "=r"(w) : "h"(p01), "h"(p23));
        {
            unsigned byteoff = (unsigned)lane * 4u;
            unsigned c = byteoff >> 4, o = byteoff & 15u;
            *(unsigned*)(g_zq + rowbase + (((c << 4) ^ rx)) + o) = w;
        }
        asm("cvt.rn.satfinite.e4m3x2.f32 %0, %1, %2;" : "=h"(p01) : "f"(v1.y*QSCALE), "f"(v1.x*QSCALE));
        asm("cvt.rn.satfinite.e4m3x2.f32 %0, %1, %2;" : "=h"(p23) : "f"(v1.w*QSCALE), "f"(v1.z*QSCALE));
        asm("mov.b32 %0, {%1, %2};" : "=r"(w) : "h"(p01), "h"(p23));
        {
            unsigned byteoff = 128u + (unsigned)lane * 4u;
            unsigned c = byteoff >> 4, o = byteoff & 15u;
            *(unsigned*)(g_zq + rowbase + (((c << 4) ^ rx)) + o) = w;
        }

        // Group partials (first half rows)
        if (nb < GBLK) {
            if (tid < 8) sg[tid] = (int)sf[nb * 8 + tid];
            __syncthreads();
            int t = tid;
            float a0 = 0.f, a1 = 0.f, a2 = 0.f, a3 = 0.f;
#pragma unroll
            for (int rr = 0; rr < 8; rr++) {
                float v = szn[rr * DIMS + t];
                int gg = sg[rr];
                a0 += (gg == 0) ? v : 0.f;
                a1 += (gg == 1) ? v : 0.f;
                a2 += (gg == 2) ? v : 0.f;
                a3 += (gg == 3) ? v : 0.f;
            }
            g_vpart[(0 * GBLK + nb) * DIMS + t] = a0;
            g_vpart[(1 * GBLK + nb) * DIMS + t] = a1;
            g_vpart[(2 * GBLK + nb) * DIMS + t] = a2;
            g_vpart[(3 * GBLK + nb) * DIMS + t] = a3;
        }

        __syncthreads();
        if (tid == 0) {
            __threadfence();
            atomicAdd(&g_tile_ready[nb >> 4], 1);
        }
        return;
    }

    // ----------------- DEN ROLE -----------------
    const unsigned sb = smem_u32(smem);
    float* scol  = (float*)(smem + 2 * TILEB);          // [2][4][64] (per pass)
    float* srow  = (float*)(smem + 2 * TILEB + 2048);   // [2][128]
    float* sposs = (float*)(smem + 2 * TILEB + 3072);   // [8]
    const int g = lane >> 2, tig = lane & 3;
    const int warpRi = wid >> 1;
    const int warpR  = warpRi * 32;
    const int warpC  = (wid & 1) * 64;

    int rem = blockIdx.x - NORMBLK, rt = 0;
    while (rem >= 64 - rt) { rem -= 64 - rt; rt++; }
    const int ct = rt + rem;
    const bool isDiag = (rt == ct);
    const bool isPos  = (ct == rt + 32);

    if (tid == 0) {
        while (ld_acquire(&g_tile_ready[rt]) < 16) { }
        if (!isDiag) while (ld_acquire(&g_tile_ready[ct]) < 16) { }
    }
    __syncthreads();

    {
        const unsigned char* As = g_zq + (size_t)rt * TILEB;
        const unsigned char* Bs = g_zq + (size_t)ct * TILEB;
#pragma unroll
        for (int i = 0; i < 8; i++) {
            unsigned o = i * 4096 + tid * 16;
            cp16(sb + o, As + o);
            if (!isDiag) cp16(sb + TILEB + o, Bs + o);
        }
        CP_COMMIT();
    }
    const unsigned sB = isDiag ? sb : (sb + TILEB);

    const int t4 = lane >> 3;
    const int rr = lane & 7;
    const unsigned hiA = (unsigned)(lane >> 4);
    const unsigned hiB = (unsigned)((lane >> 3) & 1);
    unsigned aBase[2], bBase[4];
#pragma unroll
    for (int mt = 0; mt < 2; mt++) {
        int arow = warpR + mt * 16 + ((t4 & 1) << 3) + rr;
        aBase[mt] = (unsigned)arow * 256u;
    }
#pragma unroll
    for (int q = 0; q < 4; q++) {
        int nrow = warpC + (q * 2 + (t4 >> 1)) * 8 + rr;
        bBase[q] = (unsigned)nrow * 256u;
    }

    float rs[2][2] = {{0.f, 0.f}, {0.f, 0.f}};
    float pacc = 0.f;

    CP_WAIT(0);
    __syncthreads();

#pragma unroll
    for (int pass = 0; pass < 2; pass++) {
        float acc[2][4][4];
#pragma unroll
        for (int mt = 0; mt < 2; mt++)
#pragma unroll
            for (int nt = 0; nt < 4; nt++)
#pragma unroll
                for (int qq = 0; qq < 4; qq++) acc[mt][nt][qq] = 0.f;

#pragma unroll
        for (int ks = 0; ks < 8; ks++) {
            unsigned ca = ((2u * ks + hiA) ^ (unsigned)rr) << 4;
            unsigned cb = ((2u * ks + hiB) ^ (unsigned)rr) << 4;
            unsigned a[2][4];
            LDSM4(a[0][0], a[0][1], a[0][2], a[0][3], sb + aBase[0] + ca);
            LDSM4(a[1][0], a[1][1], a[1][2], a[1][3], sb + aBase[1] + ca);
            unsigned bb2[2][4];
            LDSM4(bb2[0][0], bb2[0][1], bb2[0][2], bb2[0][3], sB + bBase[2 * pass] + cb);
            LDSM4(bb2[1][0], bb2[1][1], bb2[1][2], bb2[1][3], sB + bBase[2 * pass + 1] + cb);
#pragma unroll
            for (int mt = 0; mt < 2; mt++)
#pragma unroll
                for (int nt = 0; nt < 4; nt++)
                    MMAFP8(acc[mt][nt], a[mt], bb2[nt >> 1][(nt & 1) * 2], bb2[nt >> 1][(nt & 1) * 2 + 1]);
        }

        float cs[4][2];
#pragma unroll
        for (int nt = 0; nt < 4; nt++) { cs[nt][0] = 0.f; cs[nt][1] = 0.f; }

#pragma unroll
        for (int mt = 0; mt < 2; mt++) {
#pragma unroll
            for (int nt = 0; nt < 4; nt++) {
                if (isDiag || isPos) {
                    int r0 = warpR + mt * 16 + g;
                    int cc = warpC + (4 * pass + nt) * 8 + tig * 2;
                    bool d00 = (r0 == cc), d01 = (r0 == cc + 1);
                    bool d10 = (r0 + 8 == cc), d11 = (r0 + 8 == cc + 1);
                    if (isPos) {
                        if (d00) pacc += acc[mt][nt][0];
                        if (d01) pacc += acc[mt][nt][1];
                        if (d10) pacc += acc[mt][nt][2];
                        if (d11) pacc += acc[mt][nt][3];
                    }
                    float e0 = fexp2q(acc[mt][nt][0]);
                    float e1 = fexp2q(acc[mt][nt][1]);
                    float e2 = fexp2q(acc[mt][nt][2]);
                    float e3 = fexp2q(acc[mt][nt][3]);
                    if (isDiag) {
                        if (d00) e0 = 0.f;
                        if (d01) e1 = 0.f;
                        if (d10) e2 = 0.f;
                        if (d11) e3 = 0.f;
                    } else {
                        cs[nt][0] += e0 + e2;
                        cs[nt][1] += e1 + e3;
                    }
                    rs[mt][0] += e0 + e1;
                    rs[mt][1] += e2 + e3;
                } else {
                    float e0 = fexp2q(acc[mt][nt][0]);
                    float e1 = fexp2q(acc[mt][nt][1]);
                    float e2 = fexp2q(acc[mt][nt][2]);
                    float e3 = fexp2q(acc[mt][nt][3]);
                    cs[nt][0] += e0 + e2;
                    cs[nt][1] += e1 + e3;
                    rs[mt][0] += e0 + e1;
                    rs[mt][1] += e2 + e3;
                }
            }
        }

        if (!isDiag) {
#pragma unroll
            for (int nt = 0; nt < 4; nt++) {
#pragma unroll
                for (int jj = 0; jj < 2; jj++) {
                    float v = cs[nt][jj];
                    v += __shfl_xor_sync(0xffffffffu, v, 4);
                    v += __shfl_xor_sync(0xffffffffu, v, 8);
                    v += __shfl_xor_sync(0xffffffffu, v, 16);
                    if (lane < 4) {
                        int e = (wid & 1) * 32 + nt * 8 + lane * 2 + jj;
                        scol[pass * 256 + warpRi * 64 + e] = v;
                    }
                }
            }
        }
    }

    {
#pragma unroll
        for (int mt = 0; mt < 2; mt++)
#pragma unroll
            for (int h = 0; h < 2; h++) {
                float v = rs[mt][h];
                v += __shfl_xor_sync(0xffffffffu, v, 1);
                v += __shfl_xor_sync(0xffffffffu, v, 2);
                if (tig == 0)
                    srow[(wid & 1) * 128 + warpR + mt * 16 + h * 8 + g] = v;
            }
    }
    if (isPos) {
        pacc = warp_sum(pacc);
        if (lane == 0) sposs[wid] = pacc;
    }

    __syncthreads();

    if (wid < 2) {
        if (!isDiag) {
#pragma unroll
            for (int pass = 0; pass < 2; pass++) {
                int e = wid * 32 + lane;
                int half = e >> 5, cwi = e & 31;
                int col = half * 64 + 32 * pass + cwi;
                const float* sc = scol + pass * 256;
                float v = ((sc[0 * 64 + e] + sc[1 * 64 + e])
                         + (sc[2 * 64 + e] + sc[3 * 64 + e]));
                g_den[(size_t)rt * NTOT + ct * 128 + col] = v;
            }
        }
    } else if (wid < 4) {
        int base = (wid - 2) * 64;
#pragma unroll
        for (int k = 0; k < 2; k++) {
            int r = base + lane + k * 32;
            float v = srow[r] + srow[128 + r];
            g_den[(size_t)ct * NTOT + rt * 128 + r] = v;
        }
    } else if (wid == 4 && isPos && lane == 0) {
        float s = ((sposs[0] + sposs[1]) + (sposs[2] + sposs[3]))
                + ((sposs[4] + sposs[5]) + (sposs[6] + sposs[7]));
        g_pospart[rt] = s;
    }

    __syncthreads();
    if (tid == 0) {
        int old = atomicAdd(&g_denarrive, 1);
        if (old == DENBLK - 1) {
#pragma unroll
            for (int i = 0; i < 64; i++) g_tile_ready[i] = 0;
            g_denarrive = 0;
        }
    }
}

// ---------------------------------------------------------------------------
// Reduce kernel, grid = 260 blocks x 512:
//   b<128:  logden half-tile (64 rows, float4 loads, 2 slots/thread)
//   b<256:  vpart level-1 (16 chunks each)
//   b<260:  counts
//   Last-arriving block assembles the final scalar.
// ---------------------------------------------------------------------------
#define NRED 260

__global__ __launch_bounds__(512) void reduce_kernel(const long long* __restrict__ sf,
                                                     float* __restrict__ out) {
    const int b = blockIdx.x;
    const int t = threadIdx.x;
    __shared__ float sp[32 * 64];     // logden partials [sc][row] (8 KB)
    __shared__ float red[128];
    __shared__ int   redi[512];
    __shared__ float red2[256];
    __shared__ float sgsum[NGROUP];
    __shared__ int   slast;

    if (b < 128) {
        // logden: rows [b*64, b*64+64)
        const int rq = t & 15;        // row quad (4 rows)
        const int sc = t >> 4;        // slot chunk (2 slots)
        const int rowbase = b * 64 + rq * 4;
        float4 a0 = *(const float4*)&g_den[(size_t)(2 * sc + 0) * NTOT + rowbase];
        float4 a1 = *(const float4*)&g_den[(size_t)(2 * sc + 1) * NTOT + rowbase];
        a0.x += a1.x; a0.y += a1.y; a0.z += a1.z; a0.w += a1.w;
        // sp layout: [sc][row] = sc*64 + row
        sp[sc * 64 + rq * 4 + 0] = a0.x;
        sp[sc * 64 + rq * 4 + 1] = a0.y;
        sp[sc * 64 + rq * 4 + 2] = a0.z;
        sp[sc * 64 + rq * 4 + 3] = a0.w;
        __syncthreads();
        if (t < 64) {
            float d = 0.f;
#pragma unroll
            for (int s = 0; s < 32; s++) d += sp[s * 64 + t];
            red[t] = logf(d);
        }
        __syncthreads();
        for (int s = 32; s > 0; s >>= 1) {
            if (t < s) red[t] += red[t + s];
            __syncthreads();
        }
        if (t == 0) g_logpart[b] = red[0];
    } else if (b < 256) {
        const int bb = b - 128;               // 0..127
        const int gg = bb >> 5, seg = bb & 31;
        if (t < DIMS) {
            float v = 0.f;
#pragma unroll
            for (int ch = seg * 16; ch < seg * 16 + 16; ch++)
                v += g_vpart[(gg * GBLK + ch) * DIMS + t];
            g_vpart2[(gg * 32 + seg) * DIMS + t] = v;
        }
    } else {
        const int gg = b - 256;
        int c = 0;
#pragma unroll
        for (int r = t; r < BHALF; r += 512)
            c += ((int)sf[r] == gg);
        redi[t] = c;
        __syncthreads();
        for (int s = 256; s > 0; s >>= 1) {
            if (t < s) redi[t] += redi[t + s];
            __syncthreads();
        }
        if (t == 0) g_counts[gg] = redi[0];
    }

    __syncthreads();
    if (t == 0) {
        __threadfence();
        int old = atomicAdd(&g_arrive, 1);
        slast = (old == NRED - 1) ? 1 : 0;
    }
    __syncthreads();
    if (!slast) return;
    __threadfence();

    for (int gg = 0; gg < NGROUP; gg++) {
        if (t < 256) {
            float v = 0.f;
#pragma unroll
            for (int seg = 0; seg < 32; seg++)
                v += g_vpart2[(gg * 32 + seg) * DIMS + t];
            red2[t] = v * v;
        }
        __syncthreads();
        for (int s = 128; s > 0; s >>= 1) {
            if (t < s) red2[t] += red2[t + s];
            __syncthreads();
        }
        if (t == 0) sgsum[gg] = red2[0];
        __syncthreads();
    }

    if (t < 256) {
        float v = (t < 128) ? g_logpart[t] : 0.f;
        if (t < 32) v += g_pospart[t] * (-0.0625f);
        red2[t] = v;
    }
    __syncthreads();
    for (int s = 128; s > 0; s >>= 1) {
        if (t < s) red2[t] += red2[t + s];
        __syncthreads();
    }

    if (t == 0) {
        float contrastive = red2[0] / (float)NTOT;
        float fair_acc = 0.f, nuniq = 0.f;
        for (int gg = 0; gg < NGROUP; gg++) {
            float c = (float)g_counts[gg];
            if (c > 0.f) nuniq += 1.f;
            if (c > 1.f) fair_acc += sgsum[gg] / (c * (c - 1.f));
        }
        float fairness = 0.1f * (fair_acc / fmaxf(nuniq, 1.f));
        out[0] = contrastive + fairness;
        g_arrive = 0;                     // reset for next graph replay
    }
}

// ---------------------------------------------------------------------------
extern "C" void kernel_launch(void* const* d_in, const int* in_sizes, int n_in,
                              void* d_out, int out_size) {
    const float*     zi  = (const float*)d_in[0];
    const float*     zj  = (const float*)d_in[1];
    const long long* sf  = (const long long*)d_in[2];
    float*           out = (float*)d_out;

    cudaFuncSetAttribute(fused_kernel, cudaFuncAttributeMaxDynamicSharedMemorySize, SM_TOTAL);

    fused_kernel<<<NBLK_ALL, 256, SM_TOTAL>>>(zi, zj, sf);
    reduce_kernel<<<NRED, 512>>>(sf, out);
}